// round 13
// baseline (speedup 1.0000x reference)
#include <cuda_runtime.h>

#define NBODY  63
#define NHINGE 61
#define NSITES 16
#define QDIM   68   // 7 free-joint + 61 hinge
#define BLK    128
#define EPB    256  // elements per block (2 per thread)
#define OPAD   49   // padded output row (floats); gcd(49,32)=1 -> conflict-free STS

typedef unsigned long long u64;

// Packed f32x2 helpers (sm_103a). Both lanes independent fp32.
static __device__ __forceinline__ u64 f2pack(float lo, float hi) {
    u64 r; asm("mov.b64 %0, {%1, %2};" : "=l"(r) : "f"(lo), "f"(hi)); return r;
}
static __device__ __forceinline__ void f2unpack(u64 v, float& lo, float& hi) {
    asm("mov.b64 {%0, %1}, %2;" : "=f"(lo), "=f"(hi) : "l"(v));
}
static __device__ __forceinline__ u64 f2fma(u64 a, u64 b, u64 c) {
    u64 d; asm("fma.rn.f32x2 %0, %1, %2, %3;" : "=l"(d) : "l"(a), "l"(b), "l"(c)); return d;
}
static __device__ __forceinline__ u64 f2mul(u64 a, u64 b) {
    u64 d; asm("mul.rn.f32x2 %0, %1, %2;" : "=l"(d) : "l"(a), "l"(b)); return d;
}
static __device__ __forceinline__ u64 f2add(u64 a, u64 b) {
    u64 d; asm("add.rn.f32x2 %0, %1, %2;" : "=l"(d) : "l"(a), "l"(b)); return d;
}
static __device__ __forceinline__ u64 dupf(float x) {
    unsigned int b = __float_as_uint(x); return ((u64)b << 32) | (u64)b;
}

// Constants: per hinge 18 u64 (each = duplicated float), 16B-aligned pairs:
//  [0..3]  Q1 wxyz   [4..7] Q2 wxyz   [8..10] VC xyz
//  [11..13] -F1 xyz  [14..16] -F2 xyz [17] pad
struct FKConst {
    u64 C[NHINGE * 18];
    u64 SPd[NSITES * 3];      // duplicated site_pos
    unsigned int mask[64];    // per-body site bitmask (padded)
    unsigned int gmask[16];   // per-group (hinges 4g+1..4g+4) combined mask
};
__device__ FKConst g_fk;

#define SMEM_TOTAL (NSITES*3*8 + 64*4 + 16*4 + EPB*OPAD*4)

__global__ void fk_init(const float* __restrict__ body_pos,
                        const float* __restrict__ body_quat,
                        const float* __restrict__ hinge_axis,
                        const float* __restrict__ jnt_pos,
                        const float* __restrict__ site_pos,
                        const int*   __restrict__ site_body) {
    int t = threadIdx.x;
    if (t < 64) g_fk.mask[t] = 0u;
    if (t < NHINGE) {
        int bid = t + 2;
        float w1 = body_quat[bid*4+0], x1 = body_quat[bid*4+1];
        float y1 = body_quat[bid*4+2], z1 = body_quat[bid*4+3];
        float ax = hinge_axis[t*3+0], ay = hinge_axis[t*3+1], az = hinge_axis[t*3+2];
        u64* dst = g_fk.C + t * 18;
        dst[0] = dupf(w1); dst[1] = dupf(x1); dst[2] = dupf(y1); dst[3] = dupf(z1);
        dst[4] = dupf(-x1*ax - y1*ay - z1*az);
        dst[5] = dupf( w1*ax + y1*az - z1*ay);
        dst[6] = dupf( w1*ay - x1*az + z1*ax);
        dst[7] = dupf( w1*az + x1*ay - y1*ax);
        float jx = jnt_pos[t*3+0], jy = jnt_pos[t*3+1], jz = jnt_pos[t*3+2];
        // Rodrigues: R(ax,theta) j = e0 + cosT*e1 + sinT*e2
        float d = ax*jx + ay*jy + az*jz;
        float e0x = ax*d, e0y = ay*d, e0z = az*d;
        float e1x = jx - e0x, e1y = jy - e0y, e1z = jz - e0z;
        float e2x = ay*jz - az*jy, e2y = az*jx - ax*jz, e2z = ax*jy - ay*jx;
        auto qrot = [&](float vx, float vy, float vz, float& ox, float& oy, float& oz) {
            float tx = 2.f*(y1*vz - z1*vy);
            float ty = 2.f*(z1*vx - x1*vz);
            float tz = 2.f*(x1*vy - y1*vx);
            ox = vx + w1*tx + (y1*tz - z1*ty);
            oy = vy + w1*ty + (z1*tx - x1*tz);
            oz = vz + w1*tz + (x1*ty - y1*tx);
        };
        float f0x,f0y,f0z, f1x,f1y,f1z, f2x,f2y,f2z;
        qrot(e0x,e0y,e0z, f0x,f0y,f0z);
        qrot(e1x,e1y,e1z, f1x,f1y,f1z);
        qrot(e2x,e2y,e2z, f2x,f2y,f2z);
        dst[8]  = dupf(body_pos[bid*3+0] + jx - f0x);
        dst[9]  = dupf(body_pos[bid*3+1] + jy - f0y);
        dst[10] = dupf(body_pos[bid*3+2] + jz - f0z);
        dst[11] = dupf(-f1x); dst[12] = dupf(-f1y); dst[13] = dupf(-f1z);
        dst[14] = dupf(-f2x); dst[15] = dupf(-f2y); dst[16] = dupf(-f2z);
        dst[17] = 0;
    }
    if (t < NSITES) {
        g_fk.SPd[t*3+0] = dupf(site_pos[t*3+0]);
        g_fk.SPd[t*3+1] = dupf(site_pos[t*3+1]);
        g_fk.SPd[t*3+2] = dupf(site_pos[t*3+2]);
    }
    __syncthreads();
    if (t < NSITES)
        atomicOr(&g_fk.mask[site_body[t]], 1u << t);
    __syncthreads();
    if (t < 16) {
        // group g covers hinges 4g+1..4g+4 -> bodies 4g+3..4g+6
        unsigned int gm = 0u;
        for (int k = 0; k < 4; ++k) {
            int body = 4*t + 3 + k;
            if (body < NBODY) gm |= g_fk.mask[body];
        }
        g_fk.gmask[t] = gm;
    }
}

__global__ __launch_bounds__(BLK, 4)
void fk_main(const float* __restrict__ qpos, float* __restrict__ out, int B) {
    extern __shared__ __align__(16) u64 dynu[];
    u64* sSPd = dynu;                                   // NSITES*3
    unsigned int* sMask = (unsigned int*)(sSPd + NSITES * 3);  // 64
    unsigned int* sGM   = sMask + 64;                   // 16
    float* sOut = (float*)(sGM + 16);                   // EPB*OPAD

    const int tid = threadIdx.x;
    if (tid < NSITES * 3) sSPd[tid] = g_fk.SPd[tid];
    if (tid < 64) sMask[tid] = g_fk.mask[tid];
    if (tid < 16) sGM[tid] = g_fk.gmask[tid];
    __syncthreads();

    const int base  = blockIdx.x * EPB;
    const int nElem = (B - base < EPB) ? (B - base) : EPB;

    {
        int b0 = base + tid;        if (b0 >= B) b0 = B - 1;
        int b1 = base + tid + BLK;  if (b1 >= B) b1 = B - 1;
        const float4* q4a = (const float4*)(qpos + (size_t)b0 * QDIM);
        const float4* q4b = (const float4*)(qpos + (size_t)b1 * QDIM);
        float* soa = sOut + tid * OPAD;
        float* sob = sOut + (tid + BLK) * OPAD;

        const u64 ONE  = f2pack(1.f, 1.f);
        const u64 TWO  = f2pack(2.f, 2.f);
        const u64 NEG1 = f2pack(-1.f, -1.f);

        float4 fa0 = q4a[0], fa1 = q4a[1];
        float4 fb0 = q4b[0], fb1 = q4b[1];

        float qw0 = fa0.w, qx0 = fa1.x, qy0 = fa1.y, qz0 = fa1.z;
        float rn0 = rsqrtf(qw0*qw0 + qx0*qx0 + qy0*qy0 + qz0*qz0);
        float qw1 = fb0.w, qx1 = fb1.x, qy1 = fb1.y, qz1 = fb1.z;
        float rn1 = rsqrtf(qw1*qw1 + qx1*qx1 + qy1*qy1 + qz1*qz1);

        u64 Qw = f2pack(qw0*rn0, qw1*rn1);
        u64 Qx = f2pack(qx0*rn0, qx1*rn1);
        u64 Qy = f2pack(qy0*rn0, qy1*rn1);
        u64 Qz = f2pack(qz0*rn0, qz1*rn1);
        u64 Qxn = f2mul(Qx, NEG1), Qyn = f2mul(Qy, NEG1), Qzn = f2mul(Qz, NEG1);
        u64 Px = f2pack(fa0.x, fb0.x);
        u64 Py = f2pack(fa0.y, fb0.y);
        u64 Pz = f2pack(fa0.z, fb0.z);

        auto emit = [&](int s) {
            u64 SPx = sSPd[s*3+0], SPy = sSPd[s*3+1], SPz = sSPd[s*3+2];
            u64 Ux = f2fma(Qzn, SPy, f2mul(Qy, SPz));
            u64 Uy = f2fma(Qxn, SPz, f2mul(Qz, SPx));
            u64 Uz = f2fma(Qyn, SPx, f2mul(Qx, SPy));
            u64 Cx = f2fma(Qzn, Uy, f2mul(Qy, Uz));
            u64 Cy = f2fma(Qxn, Uz, f2mul(Qz, Ux));
            u64 Cz = f2fma(Qyn, Ux, f2mul(Qx, Uy));
            u64 Qw2 = f2add(Qw, Qw);
            u64 Rx = f2fma(TWO, Cx, f2fma(Qw2, Ux, f2add(Px, SPx)));
            u64 Ry = f2fma(TWO, Cy, f2fma(Qw2, Uy, f2add(Py, SPy)));
            u64 Rz = f2fma(TWO, Cz, f2fma(Qw2, Uz, f2add(Pz, SPz)));
            float a, b;
            f2unpack(Rx, a, b); soa[s*3+0] = a; sob[s*3+0] = b;
            f2unpack(Ry, a, b); soa[s*3+1] = a; sob[s*3+1] = b;
            f2unpack(Rz, a, b); soa[s*3+2] = a; sob[s*3+2] = b;
        };

        auto sites = [&](int body) {
            unsigned int mm = sMask[body];
            while (mm) {
                int s = __ffs(mm) - 1; mm &= mm - 1;
                emit(s);
            }
        };

        // Pure hinge core: packed math only, no branches.
        auto core = [&](int h, u64 SN, u64 CS) {
            const u64* C = g_fk.C + h * 18;
            ulonglong2 c01 = __ldg((const ulonglong2*)(C + 0));
            ulonglong2 c23 = __ldg((const ulonglong2*)(C + 2));
            ulonglong2 c45 = __ldg((const ulonglong2*)(C + 4));
            ulonglong2 c67 = __ldg((const ulonglong2*)(C + 6));
            ulonglong2 c89 = __ldg((const ulonglong2*)(C + 8));
            ulonglong2 cAB = __ldg((const ulonglong2*)(C + 10));
            ulonglong2 cCD = __ldg((const ulonglong2*)(C + 12));
            ulonglong2 cEF = __ldg((const ulonglong2*)(C + 14));
            u64 cG = __ldg(C + 16);

            // lq = cs*Q1 + sn*Q2
            u64 Lw = f2fma(CS, c01.x, f2mul(SN, c45.x));
            u64 Lx = f2fma(CS, c01.y, f2mul(SN, c45.y));
            u64 Ly = f2fma(CS, c23.x, f2mul(SN, c67.x));
            u64 Lz = f2fma(CS, c23.y, f2mul(SN, c67.y));

            // nq = q (x) lq, minus terms via negated copies
            u64 Nw = f2fma(Qzn, Lz, f2fma(Qyn, Ly, f2fma(Qxn, Lx, f2mul(Qw, Lw))));
            u64 Nx = f2fma(Qzn, Ly, f2fma(Qy,  Lz, f2fma(Qx,  Lw, f2mul(Qw, Lx))));
            u64 Ny = f2fma(Qz,  Lx, f2fma(Qy,  Lw, f2fma(Qxn, Lz, f2mul(Qw, Ly))));
            u64 Nz = f2fma(Qz,  Lw, f2fma(Qyn, Lx, f2fma(Qx,  Ly, f2mul(Qw, Lz))));

            // full-angle sin/cos from half-angle
            u64 S2   = f2add(SN, SN);
            u64 SinT = f2mul(S2, CS);
            u64 SNn  = f2mul(SN, NEG1);
            u64 CosT = f2fma(SNn, S2, ONE);

            // g = VC + cosT*(-F1) + sinT*(-F2)
            u64 Gx = f2fma(CosT, cAB.y, f2fma(SinT, cEF.x, c89.x));
            u64 Gy = f2fma(CosT, cCD.x, f2fma(SinT, cEF.y, c89.y));
            u64 Gz = f2fma(CosT, cCD.y, f2fma(SinT, cG,    cAB.x));

            // wp += g + 2w(qxg) + 2 qx(qxg)   (rotate by OLD quat)
            u64 Tx = f2fma(Qzn, Gy, f2mul(Qy, Gz));
            u64 Ty = f2fma(Qxn, Gz, f2mul(Qz, Gx));
            u64 Tz = f2fma(Qyn, Gx, f2mul(Qx, Gy));
            u64 Cx = f2fma(Qzn, Ty, f2mul(Qy, Tz));
            u64 Cy = f2fma(Qxn, Tz, f2mul(Qz, Tx));
            u64 Cz = f2fma(Qyn, Tx, f2mul(Qx, Ty));
            u64 Qw2 = f2add(Qw, Qw);
            Px = f2add(Px, f2fma(TWO, Cx, f2fma(Qw2, Tx, Gx)));
            Py = f2add(Py, f2fma(TWO, Cy, f2fma(Qw2, Ty, Gy)));
            Pz = f2add(Pz, f2fma(TWO, Cz, f2fma(Qw2, Tz, Gz)));

            Qw = Nw; Qx = Nx; Qy = Ny; Qz = Nz;
            Qxn = f2mul(Qx, NEG1); Qyn = f2mul(Qy, NEG1); Qzn = f2mul(Qz, NEG1);
        };

        // body 1 sites
        sites(1);

        // h = 0 (body 2), then 15 groups of 4 hinges
        {
            float s0a, c0a, s0b, c0b;
            __sincosf(0.5f * fa1.w, &s0a, &c0a);
            __sincosf(0.5f * fb1.w, &s0b, &c0b);
            core(0, f2pack(s0a, s0b), f2pack(c0a, c0b));
            sites(2);
        }
        float4 ava = q4a[2];
        float4 avb = q4b[2];
        #pragma unroll 1
        for (int g = 0; g < 15; ++g) {
            float4 ca = ava, cb = avb;
            if (g < 14) { ava = q4a[3 + g]; avb = q4b[3 + g]; }
            float sa, cA, sb, cB;
            __sincosf(0.5f * ca.x, &sa, &cA);
            __sincosf(0.5f * cb.x, &sb, &cB);
            u64 SN0 = f2pack(sa, sb), CS0 = f2pack(cA, cB);
            __sincosf(0.5f * ca.y, &sa, &cA);
            __sincosf(0.5f * cb.y, &sb, &cB);
            u64 SN1 = f2pack(sa, sb), CS1 = f2pack(cA, cB);
            __sincosf(0.5f * ca.z, &sa, &cA);
            __sincosf(0.5f * cb.z, &sb, &cB);
            u64 SN2 = f2pack(sa, sb), CS2 = f2pack(cA, cB);
            __sincosf(0.5f * ca.w, &sa, &cA);
            __sincosf(0.5f * cb.w, &sb, &cB);
            u64 SN3 = f2pack(sa, sb), CS3 = f2pack(cA, cB);

            int h = 4*g + 1;
            if (sGM[g] == 0u) {
                // hot path: one branch-free basic block of 4 hinges
                core(h + 0, SN0, CS0);
                core(h + 1, SN1, CS1);
                core(h + 2, SN2, CS2);
                core(h + 3, SN3, CS3);
            } else {
                core(h + 0, SN0, CS0); sites(h + 2);
                core(h + 1, SN1, CS1); sites(h + 3);
                core(h + 2, SN2, CS2); sites(h + 4);
                core(h + 3, SN3, CS3); sites(h + 5);
            }
        }
    }

    __syncthreads();

    // Cooperative coalesced store: gather from padded rows, STG.128 contiguous
    {
        float4* ov = (float4*)(out + (size_t)base * 48);
        int total4 = nElem * 12;   // 12 float4 per element
        for (int i = tid; i < total4; i += BLK) {
            int e = i / 12;
            int j = i - e * 12;
            const float* src = sOut + e * OPAD + j * 4;
            ov[i] = make_float4(src[0], src[1], src[2], src[3]);
        }
    }
}

extern "C" void kernel_launch(void* const* d_in, const int* in_sizes, int n_in,
                              void* d_out, int out_size) {
    const float* qpos       = (const float*)d_in[0];
    const float* body_pos   = (const float*)d_in[1];
    const float* body_quat  = (const float*)d_in[2];
    const float* hinge_axis = (const float*)d_in[3];
    const float* jnt_pos    = (const float*)d_in[4];
    const float* site_pos   = (const float*)d_in[5];
    const int*   site_body  = (const int*)d_in[7];

    int B = in_sizes[0] / QDIM;

    static int attrs_set = 0;
    if (!attrs_set) {
        cudaFuncSetAttribute(fk_main, cudaFuncAttributeMaxDynamicSharedMemorySize, SMEM_TOTAL);
        cudaFuncSetAttribute(fk_main, cudaFuncAttributePreferredSharedMemoryCarveout, 100);
        attrs_set = 1;
    }

    fk_init<<<1, 64>>>(body_pos, body_quat, hinge_axis, jnt_pos, site_pos, site_body);
    fk_main<<<(B + EPB - 1) / EPB, BLK, SMEM_TOTAL>>>(qpos, (float*)d_out, B);
}

// round 14
// speedup vs baseline: 1.3270x; 1.3270x over previous
#include <cuda_runtime.h>

#define NBODY  63
#define NHINGE 61
#define NSITES 16
#define QDIM   68   // 7 free-joint + 61 hinge
#define BLK    128
#define OPAD   49   // padded output row (floats); gcd(49,32)=1 -> conflict-free STS

// Per-hinge folded constants + site metadata, produced by fk_init each launch.
struct FKConst {
    float4 Q1[NHINGE];        // body_quat[bid]              (w,x,y,z)
    float4 Q2[NHINGE];        // qmul(body_quat[bid],(0,ax)) (w,x,y,z)
    float4 VC[NHINGE];        // body_pos + jnt_pos - f0
    float4 F1[NHINGE];        // R(Q1)(j - ax(ax.j))
    float4 F2[NHINGE];        // R(Q1)(ax x j)
    float4 SP[NSITES];        // site_pos
    unsigned int mask[NBODY]; // bitmask of sites attached to each body
    unsigned int gmask[16];   // combined mask of bodies 4g+3..4g+6 (hinges 4g+1..4g+4)
};
__device__ FKConst g_fk;

__global__ void fk_init(const float* __restrict__ body_pos,
                        const float* __restrict__ body_quat,
                        const float* __restrict__ hinge_axis,
                        const float* __restrict__ jnt_pos,
                        const float* __restrict__ site_pos,
                        const int*   __restrict__ site_body) {
    int t = threadIdx.x;
    if (t < NBODY) g_fk.mask[t] = 0u;
    if (t < NHINGE) {
        int bid = t + 2;
        float w1 = body_quat[bid*4+0], x1 = body_quat[bid*4+1];
        float y1 = body_quat[bid*4+2], z1 = body_quat[bid*4+3];
        float ax = hinge_axis[t*3+0], ay = hinge_axis[t*3+1], az = hinge_axis[t*3+2];
        g_fk.Q1[t] = make_float4(w1, x1, y1, z1);
        g_fk.Q2[t] = make_float4(-x1*ax - y1*ay - z1*az,
                                  w1*ax + y1*az - z1*ay,
                                  w1*ay - x1*az + z1*ax,
                                  w1*az + x1*ay - y1*ax);
        float jx = jnt_pos[t*3+0], jy = jnt_pos[t*3+1], jz = jnt_pos[t*3+2];
        // Rodrigues: R(ax,theta) j = e0 + cosT*e1 + sinT*e2
        float d = ax*jx + ay*jy + az*jz;
        float e0x = ax*d, e0y = ay*d, e0z = az*d;
        float e1x = jx - e0x, e1y = jy - e0y, e1z = jz - e0z;
        float e2x = ay*jz - az*jy, e2y = az*jx - ax*jz, e2z = ax*jy - ay*jx;
        auto qrot = [&](float vx, float vy, float vz, float& ox, float& oy, float& oz) {
            float tx = 2.f*(y1*vz - z1*vy);
            float ty = 2.f*(z1*vx - x1*vz);
            float tz = 2.f*(x1*vy - y1*vx);
            ox = vx + w1*tx + (y1*tz - z1*ty);
            oy = vy + w1*ty + (z1*tx - x1*tz);
            oz = vz + w1*tz + (x1*ty - y1*tx);
        };
        float f0x,f0y,f0z, f1x,f1y,f1z, f2x,f2y,f2z;
        qrot(e0x,e0y,e0z, f0x,f0y,f0z);
        qrot(e1x,e1y,e1z, f1x,f1y,f1z);
        qrot(e2x,e2y,e2z, f2x,f2y,f2z);
        g_fk.VC[t] = make_float4(body_pos[bid*3+0] + jx - f0x,
                                 body_pos[bid*3+1] + jy - f0y,
                                 body_pos[bid*3+2] + jz - f0z, 0.f);
        g_fk.F1[t] = make_float4(f1x, f1y, f1z, 0.f);
        g_fk.F2[t] = make_float4(f2x, f2y, f2z, 0.f);
    }
    if (t < NSITES)
        g_fk.SP[t] = make_float4(site_pos[t*3+0], site_pos[t*3+1], site_pos[t*3+2], 0.f);
    __syncthreads();
    if (t < NSITES)
        atomicOr(&g_fk.mask[site_body[t]], 1u << t);
    __syncthreads();
    if (t < 16) {
        unsigned int gm = 0u;
        for (int k = 0; k < 4; ++k) {
            int body = 4*t + 3 + k;
            if (body < NBODY) gm |= g_fk.mask[body];
        }
        g_fk.gmask[t] = gm;
    }
}

__global__ __launch_bounds__(BLK, 7)
void fk_main(const float* __restrict__ qpos, float* __restrict__ out, int B) {
    __shared__ float4 sQ1[NHINGE], sQ2[NHINGE], sVC[NHINGE], sF1[NHINGE], sF2[NHINGE];
    __shared__ float4 sSP[NSITES];
    __shared__ unsigned int sMask[NBODY];
    __shared__ unsigned int sGM[16];
    __shared__ __align__(16) float sOut[BLK * OPAD];

    for (int i = threadIdx.x; i < NHINGE; i += BLK) {
        sQ1[i] = g_fk.Q1[i]; sQ2[i] = g_fk.Q2[i];
        sVC[i] = g_fk.VC[i]; sF1[i] = g_fk.F1[i]; sF2[i] = g_fk.F2[i];
    }
    if (threadIdx.x < NSITES) sSP[threadIdx.x] = g_fk.SP[threadIdx.x];
    if (threadIdx.x < NBODY)  sMask[threadIdx.x] = g_fk.mask[threadIdx.x];
    if (threadIdx.x < 16)     sGM[threadIdx.x] = g_fk.gmask[threadIdx.x];
    __syncthreads();

    const int base  = blockIdx.x * BLK;
    const int tid   = threadIdx.x;
    const int b     = base + tid;
    const int nElem = (B - base < BLK) ? (B - base) : BLK;

    if (tid < nElem) {
        const float4* q4 = (const float4*)(qpos + (size_t)b * QDIM);
        float* so = sOut + tid * OPAD;

        float4 f0 = q4[0];                 // wp.xyz, quat.w
        float4 f1 = q4[1];                 // quat.xyz, angle[0]
        float wpx = f0.x, wpy = f0.y, wpz = f0.z;
        float qw = f0.w, qx = f1.x, qy = f1.y, qz = f1.z;
        float rn = rsqrtf(qw*qw + qx*qx + qy*qy + qz*qz);
        qw *= rn; qx *= rn; qy *= rn; qz *= rn;

        auto emit = [&](int s) {
            float4 sp = sSP[s];
            float ux = 2.f*(qy*sp.z - qz*sp.y);
            float uy = 2.f*(qz*sp.x - qx*sp.z);
            float uz = 2.f*(qx*sp.y - qy*sp.x);
            so[s*3+0] = wpx + sp.x + qw*ux + (qy*uz - qz*uy);
            so[s*3+1] = wpy + sp.y + qw*uy + (qz*ux - qx*uz);
            so[s*3+2] = wpz + sp.z + qw*uz + (qx*uy - qy*ux);
        };
        auto sites = [&](int body) {
            unsigned int mm = sMask[body];
            while (mm) {
                int s = __ffs(mm) - 1; mm &= mm - 1;
                emit(s);
            }
        };

        // Pure hinge core: no branches, no site handling.
        auto core = [&](int h, float sn, float cs) {
            float4 Q1 = sQ1[h], Q2 = sQ2[h];
            float lw = cs*Q1.x + sn*Q2.x;
            float lx = cs*Q1.y + sn*Q2.y;
            float ly = cs*Q1.z + sn*Q2.z;
            float lz = cs*Q1.w + sn*Q2.w;

            float nw = qw*lw - qx*lx - qy*ly - qz*lz;
            float nx = qw*lx + qx*lw + qy*lz - qz*ly;
            float ny = qw*ly - qx*lz + qy*lw + qz*lx;
            float nz = qw*lz + qx*ly - qy*lx + qz*lw;

            float s2   = sn + sn;
            float sinT = s2 * cs;
            float cosT = fmaf(-sn, s2, 1.f);

            float4 Vc = sVC[h], F1 = sF1[h], F2 = sF2[h];
            float gx = Vc.x - cosT*F1.x - sinT*F2.x;
            float gy = Vc.y - cosT*F1.y - sinT*F2.y;
            float gz = Vc.z - cosT*F1.z - sinT*F2.z;

            float tx = 2.f*(qy*gz - qz*gy);
            float ty = 2.f*(qz*gx - qx*gz);
            float tz = 2.f*(qx*gy - qy*gx);
            wpx += gx + qw*tx + (qy*tz - qz*ty);
            wpy += gy + qw*ty + (qz*tx - qx*tz);
            wpz += gz + qw*tz + (qx*ty - qy*tx);

            qw = nw; qx = nx; qy = ny; qz = nz;
        };

        // body 1 sites
        sites(1);

        // h = 0 (body 2), then 15 groups of 4 hinges with group-level site masks
        {
            float s0, c0;
            __sincosf(0.5f * f1.w, &s0, &c0);
            core(0, s0, c0);
            sites(2);
        }
        float4 av = q4[2];
        #pragma unroll 1
        for (int g = 0; g < 15; ++g) {
            float4 cur = av;
            if (g < 14) av = q4[3 + g];
            float sa, ca, sb, cb, sc, cc, sd, cd;
            __sincosf(0.5f * cur.x, &sa, &ca);
            __sincosf(0.5f * cur.y, &sb, &cb);
            __sincosf(0.5f * cur.z, &sc, &cc);
            __sincosf(0.5f * cur.w, &sd, &cd);

            int h = 4*g + 1;
            if (sGM[g] == 0u) {
                // hot path: 4 hinges in one branch-free basic block
                core(h + 0, sa, ca);
                core(h + 1, sb, cb);
                core(h + 2, sc, cc);
                core(h + 3, sd, cd);
            } else {
                core(h + 0, sa, ca); sites(h + 2);
                core(h + 1, sb, cb); sites(h + 3);
                core(h + 2, sc, cc); sites(h + 4);
                core(h + 3, sd, cd); sites(h + 5);
            }
        }
    }

    __syncthreads();

    // Cooperative coalesced store: gather from padded rows, STG.128 contiguous
    {
        float4* ov = (float4*)(out + (size_t)base * 48);
        int total4 = nElem * 12;   // 12 float4 per element
        for (int i = tid; i < total4; i += BLK) {
            int e = i / 12;
            int j = i - e * 12;
            const float* src = sOut + e * OPAD + j * 4;
            ov[i] = make_float4(src[0], src[1], src[2], src[3]);
        }
    }
}

extern "C" void kernel_launch(void* const* d_in, const int* in_sizes, int n_in,
                              void* d_out, int out_size) {
    const float* qpos       = (const float*)d_in[0];
    const float* body_pos   = (const float*)d_in[1];
    const float* body_quat  = (const float*)d_in[2];
    const float* hinge_axis = (const float*)d_in[3];
    const float* jnt_pos    = (const float*)d_in[4];
    const float* site_pos   = (const float*)d_in[5];
    const int*   site_body  = (const int*)d_in[7];

    int B = in_sizes[0] / QDIM;

    static int carveout_set = 0;
    if (!carveout_set) {
        cudaFuncSetAttribute(fk_main, cudaFuncAttributePreferredSharedMemoryCarveout, 100);
        carveout_set = 1;
    }

    fk_init<<<1, 64>>>(body_pos, body_quat, hinge_axis, jnt_pos, site_pos, site_body);
    fk_main<<<(B + BLK - 1) / BLK, BLK>>>(qpos, (float*)d_out, B);
}